// round 15
// baseline (speedup 1.0000x reference)
#include <cuda_runtime.h>

#define BB 512
#define LL 1024
#define DD 16
#define HH 64
#define G3 192      // 3*H
#define NB 7        // sequences per CTA
#define NTHREADS 384
#define NCTA_PER_DIR 74   // 148 CTAs total = 1/SM
#define HROW 72     // padded h row: chunk0 cols @ [0,32), chunk1 cols @ [36,68)
#define NGI (NB * G3 / 4)   // 336 float4 gi entries per step per CTA

typedef unsigned long long ull;

// scratch: y_f / y_b
__device__ float g_scratch[2 * BB * LL];
// precomputed input projection gi[dir][b][t][192] (includes bih)
#define GI_TOTAL (2 * BB * LL * G3)
__device__ float g_gi[(size_t)GI_TOTAL];

__device__ __forceinline__ void fma2(ull &acc, ull a, ull b) {
    asm("fma.rn.f32x2 %0, %1, %2, %0;" : "+l"(acc) : "l"(a), "l"(b));
}
__device__ __forceinline__ float unpack_sum(ull v) {
    float lo, hi;
    asm("mov.b64 {%0, %1}, %2;" : "=f"(lo), "=f"(hi) : "l"(v));
    return lo + hi;
}
__device__ __forceinline__ ull pack2(float lo, float hi) {
    ull r;
    asm("mov.b64 %0, {%1, %2};" : "=l"(r) : "f"(lo), "f"(hi));
    return r;
}
__device__ __forceinline__ ull add2(ull a, ull b) {
    ull r;
    asm("add.rn.f32x2 %0, %1, %2;" : "=l"(r) : "l"(a), "l"(b));
    return r;
}
__device__ __forceinline__ void unpack2(ull v, float &lo, float &hi) {
    asm("mov.b64 {%0, %1}, %2;" : "=f"(lo), "=f"(hi) : "l"(v));
}
__device__ __forceinline__ float sigmoidf_(float x) {
    return 1.0f / (1.0f + __expf(-x));
}
__device__ __forceinline__ float tanhf_(float x) {
    float ax = fabsf(x);
    float e  = __expf(2.0f * ax);          // inf-safe
    float t  = 1.0f - 2.0f / (e + 1.0f);
    return copysignf(t, x);
}

__global__ void brios_dummy_kernel() {}   // ncu launch-skip alignment

// ---- precompute gi = Wih . x + bih for all (dir, b, t) ----
__global__ void gi_precompute_kernel(
    const float* __restrict__ x,
    const float* __restrict__ fWih, const float* __restrict__ fbih,
    const float* __restrict__ bWih, const float* __restrict__ bbih)
{
    int i = blockIdx.x * 256 + threadIdx.x;
    if (i >= GI_TOTAL) return;
    const int per_dir = BB * LL * G3;
    int dirp = i / per_dir;
    int rem  = i - dirp * per_dir;
    int j    = rem % G3;
    int bt   = rem / G3;
    const float* W = dirp ? bWih : fWih;
    float acc = dirp ? bbih[j] : fbih[j];
    const float4* xp = reinterpret_cast<const float4*>(x + (size_t)bt * DD);
    const float4* wp = reinterpret_cast<const float4*>(W + j * DD);
    #pragma unroll
    for (int q = 0; q < 4; q++) {
        float4 xv = xp[q], wv = wp[q];
        acc = fmaf(wv.x, xv.x, acc);
        acc = fmaf(wv.y, xv.y, acc);
        acc = fmaf(wv.z, xv.z, acc);
        acc = fmaf(wv.w, xv.w, acc);
    }
    g_gi[i] = acc;
}

// One fused step for NSEQ sequences starting at SBASE.
// Thread owns Whh rows {u, 64+u, 128+u} x cols [chunk*32, chunk*32+32).
template<int NSEQ>
__device__ __forceinline__ void step_work(
    int SBASE, int chunk, int u, int w4, int hslot,
    const ull (&whh2)[3][16], const float (&bhh3)[3], float wout_u,
    const float* __restrict__ h_rd, float* __restrict__ h_wr,
    const float* __restrict__ gi_rd,       // flattened [NB][G3], has bih folded
    const float* __restrict__ decay_rd, float* __restrict__ ypart_wr)
{
    ull acc[NSEQ][3];
    #pragma unroll
    for (int s = 0; s < NSEQ; s++) { acc[s][0] = 0; acc[s][1] = 0; acc[s][2] = 0; }

    #pragma unroll
    for (int kp = 0; kp < 8; kp++) {          // 8 x 16B = 32 cols (half row)
        #pragma unroll
        for (int s = 0; s < NSEQ; s++) {
            ulonglong2 hh = reinterpret_cast<const ulonglong2*>(
                h_rd + (SBASE + s) * HROW + chunk * 36)[kp];
            fma2(acc[s][0], whh2[0][2 * kp],     hh.x);
            fma2(acc[s][0], whh2[0][2 * kp + 1], hh.y);
            fma2(acc[s][1], whh2[1][2 * kp],     hh.x);
            fma2(acc[s][1], whh2[1][2 * kp + 1], hh.y);
            fma2(acc[s][2], whh2[2][2 * kp],     hh.x);
            fma2(acc[s][2], whh2[2][2 * kp + 1], hh.y);
        }
    }

    // combine column halves: pack pairs of dots, one shfl_xor(1) each
    float ghs[3 * NSEQ];
    {
        float vals[3 * NSEQ];
        #pragma unroll
        for (int s = 0; s < NSEQ; s++) {
            vals[s * 3 + 0] = unpack_sum(acc[s][0]);
            vals[s * 3 + 1] = unpack_sum(acc[s][1]);
            vals[s * 3 + 2] = unpack_sum(acc[s][2]);
        }
        constexpr int NP = (3 * NSEQ + 1) / 2;
        #pragma unroll
        for (int p = 0; p < NP; p++) {
            float hi = (2 * p + 1 < 3 * NSEQ) ? vals[2 * p + 1] : 0.0f;
            ull P = pack2(vals[2 * p], hi);
            P = add2(P, __shfl_xor_sync(0xffffffffu, P, 1));
            float a, b;
            unpack2(P, a, b);
            ghs[2 * p] = a;
            if (2 * p + 1 < 3 * NSEQ) ghs[2 * p + 1] = b;
        }
    }

    // gate: lane parity (=chunk) handles seq 2*pair+chunk
    #pragma unroll
    for (int pair = 0; pair < (NSEQ + 1) / 2; pair++) {
        const int s0i = 2 * pair;
        const int s1i = (2 * pair + 1 < NSEQ) ? (2 * pair + 1) : 0;
        const bool valid = !(chunk && (2 * pair + 1 >= NSEQ));
        const int smi = chunk ? s1i : s0i;
        float c = 0.0f;
        int S = SBASE + smi;
        if (valid) {
            float GR = chunk ? ghs[s1i * 3 + 0] : ghs[s0i * 3 + 0];
            float GZ = chunk ? ghs[s1i * 3 + 1] : ghs[s0i * 3 + 1];
            float GN = chunk ? ghs[s1i * 3 + 2] : ghs[s0i * 3 + 2];
            float IR = gi_rd[S * G3 + u];
            float IZ = gi_rd[S * G3 + HH + u];
            float IN = gi_rd[S * G3 + 2 * HH + u];
            float dk = decay_rd[S];
            float rr = sigmoidf_(IR + fmaf(dk, GR, bhh3[0]));
            float zz = sigmoidf_(IZ + fmaf(dk, GZ, bhh3[1]));
            float nn = tanhf_   (IN + rr * fmaf(dk, GN, bhh3[2]));
            float hb = h_rd[S * HROW + hslot] * dk;
            float hnew = (1.0f - zz) * nn + zz * hb;
            h_wr[S * HROW + hslot] = hnew;
            c = hnew * wout_u;
        }
        c += __shfl_xor_sync(0xffffffffu, c, 2);
        c += __shfl_xor_sync(0xffffffffu, c, 4);
        c += __shfl_xor_sync(0xffffffffu, c, 8);
        c += __shfl_xor_sync(0xffffffffu, c, 16);
        if (valid && ((threadIdx.x & 31) < 2))
            ypart_wr[S * 4 + w4] = c;
    }
}

__global__ __launch_bounds__(NTHREADS, 1)
void brios_main_kernel(
    const float* __restrict__ dt,
    const float* __restrict__ f_Whh, const float* __restrict__ f_bhh,
    const float* __restrict__ f_gamma, const float* __restrict__ f_Wout,
    const float* __restrict__ f_bout,
    const float* __restrict__ b_Whh, const float* __restrict__ b_bhh,
    const float* __restrict__ b_gamma, const float* __restrict__ b_Wout,
    const float* __restrict__ b_bout)
{
    __shared__ __align__(16) float h_sh[2][NB * HROW];
    __shared__ __align__(16) float gi_sh[2][NB * G3];
    __shared__ float decay_sh[2][8];
    __shared__ __align__(16) float ypart[2][NB * 4];

    const int tid  = threadIdx.x;
    const int dir  = blockIdx.x / NCTA_PER_DIR;
    const int tile = blockIdx.x % NCTA_PER_DIR;
    const int b0   = tile * NB;

    const float* Whh  = dir ? b_Whh  : f_Whh;
    const float* bhh  = dir ? b_bhh  : f_bhh;
    const float* Wout = dir ? b_Wout : f_Wout;
    const float  bout0 = dir ? b_bout[0] : f_bout[0];
    float g = dir ? b_gamma[0] : f_gamma[0];
    g = fminf(fmaxf(g, 1e-4f), 10.0f);

    float* yout = g_scratch + dir * (BB * LL);

    // group: 0 -> seqs 0-2 (NSEQ 3), 1 -> seqs 3-4, 2 -> seqs 5-6 + staging
    const int sg    = tid >> 7;
    const int u     = (tid & 127) >> 1;
    const int chunk = tid & 1;
    const int w4    = (tid >> 5) & 3;
    const int hslot = u + ((u >> 5) << 2);

    // ---- resident weights: gate-triplet rows {u, 64+u, 128+u}, col half ----
    ull whh2[3][16];
    float bhh3[3];
    #pragma unroll
    for (int r = 0; r < 3; r++) {
        int row = u + r * HH;
        const ull* p = reinterpret_cast<const ull*>(Whh + row * HH + chunk * 32);
        #pragma unroll
        for (int k = 0; k < 16; k++) whh2[r][k] = p[k];
        bhh3[r] = bhh[row];
    }
    const float wout_u = Wout[u];

    // staging roles
    const bool is_gi = (tid < NGI);                   // 336 gi loaders
    int gs = 0, gq = 0;
    const float4* gi_base = nullptr;
    if (is_gi) {
        gs = tid / 48; gq = tid % 48;
        int bb = min(b0 + gs, BB - 1);
        gi_base = reinterpret_cast<const float4*>(
            g_gi + ((size_t)(dir * BB + bb) * LL) * G3) + gq;
    }
    const bool is_d = (tid >= NGI) && (tid < NGI + NB);
    const int  ds   = tid - NGI;
    int d_bb = 0;
    if (is_d) d_bb = min(b0 + ds, BB - 1);

    // zero both h buffers
    for (int i = tid; i < 2 * NB * HROW; i += NTHREADS) ((float*)h_sh)[i] = 0.0f;

    // ---- prologue: gi(0)->smem, gi(1)->reg; decay(0); dt(1)->reg ----
    float4 giR = make_float4(0.f, 0.f, 0.f, 0.f);
    float dtr = 0.0f;
    {
        int t0a = dir ? (LL - 1) : 0;       // actual time of step 0
        int t1a = dir ? (LL - 2) : 1;       // actual time of step 1
        if (is_gi) {
            reinterpret_cast<float4*>(gi_sh[0])[tid] = gi_base[(size_t)t0a * 48];
            giR = gi_base[(size_t)t1a * 48];
        }
        if (is_d) {
            float dc = fminf(fmaxf(dt[d_bb * LL + t0a], 0.0f), 1.0e6f);
            decay_sh[0][ds] = __expf(-g * dc);
            dtr = dt[d_bb * LL + t1a];
        }
    }
    __syncthreads();

    for (int t = 0; t < LL; t++) {
        const int cb = t & 1;
        const int pb = cb ^ 1;

        // ---- staging first (issue LDG early): gi/decay for t+1, fetch t+2 ----
        if (is_gi) {
            reinterpret_cast<float4*>(gi_sh[pb])[tid] = giR;   // gi for step t+1
            int tn  = (t + 2 < LL) ? (t + 2) : (LL - 1);
            int ttn = dir ? (LL - 1 - tn) : tn;
            giR = gi_base[(size_t)ttn * 48];
        }
        if (is_d) {
            if (t > 0) {
                int b = b0 + ds;
                if (b < BB) {
                    int tprev = dir ? (LL - t) : (t - 1);
                    const float4* yp =
                        reinterpret_cast<const float4*>(&ypart[pb][ds * 4]);
                    float4 a = yp[0];
                    yout[b * LL + tprev] = a.x + a.y + a.z + a.w + bout0;
                }
            }
            float dc = fminf(fmaxf(dtr, 0.0f), 1.0e6f);
            decay_sh[pb][ds] = __expf(-g * dc);
            int tn  = (t + 2 < LL) ? (t + 2) : (LL - 1);
            int ttn = dir ? (LL - 1 - tn) : tn;
            dtr = dt[d_bb * LL + ttn];
        }

        // ---- matvec + gate ----
        if (sg == 0) {
            step_work<3>(0, chunk, u, w4, hslot, whh2, bhh3, wout_u,
                         h_sh[pb], h_sh[cb], gi_sh[cb], decay_sh[cb], ypart[cb]);
        } else if (sg == 1) {
            step_work<2>(3, chunk, u, w4, hslot, whh2, bhh3, wout_u,
                         h_sh[pb], h_sh[cb], gi_sh[cb], decay_sh[cb], ypart[cb]);
        } else {
            step_work<2>(5, chunk, u, w4, hslot, whh2, bhh3, wout_u,
                         h_sh[pb], h_sh[cb], gi_sh[cb], decay_sh[cb], ypart[cb]);
        }
        __syncthreads();
    }

    // final y (step t = L-1)
    if (tid < NB) {
        int b = b0 + tid;
        if (b < BB) {
            int tlast = dir ? 0 : (LL - 1);
            const float4* yp =
                reinterpret_cast<const float4*>(&ypart[(LL - 1) & 1][tid * 4]);
            float4 a = yp[0];
            yout[b * LL + tlast] = a.x + a.y + a.z + a.w + bout0;
        }
    }
}

__global__ void brios_combine_kernel(float* __restrict__ out, int full) {
    int i = blockIdx.x * blockDim.x + threadIdx.x;
    const int n = BB * LL;
    if (i < n) {
        float a = g_scratch[i];          // y_f
        float b = g_scratch[n + i];      // y_b
        out[i] = 0.5f * (a + b);
        if (full) {
            out[n + i]     = a;
            out[2 * n + i] = b;
        }
    }
}

extern "C" void kernel_launch(void* const* d_in, const int* in_sizes, int n_in,
                              void* d_out, int out_size) {
    const float* x       = (const float*)d_in[0];
    const float* dt      = (const float*)d_in[1];
    const float* f_Wih   = (const float*)d_in[2];
    const float* f_Whh   = (const float*)d_in[3];
    const float* f_bih   = (const float*)d_in[4];
    const float* f_bhh   = (const float*)d_in[5];
    const float* f_gamma = (const float*)d_in[6];
    const float* f_Wout  = (const float*)d_in[7];
    const float* f_bout  = (const float*)d_in[8];
    const float* b_Wih   = (const float*)d_in[9];
    const float* b_Whh   = (const float*)d_in[10];
    const float* b_bih   = (const float*)d_in[11];
    const float* b_bhh   = (const float*)d_in[12];
    const float* b_gamma = (const float*)d_in[13];
    const float* b_Wout  = (const float*)d_in[14];
    const float* b_bout  = (const float*)d_in[15];
    float* out = (float*)d_out;

    // 3 dummies: aligns ncu "-s 5 -c 1" onto the kernel after them (verified R12:
    // with gi_precompute now in front, ncu lands on gi_precompute or main; both useful)
    for (int i = 0; i < 2; i++) brios_dummy_kernel<<<1, 32>>>();

    gi_precompute_kernel<<<(GI_TOTAL + 255) / 256, 256>>>(
        x, f_Wih, f_bih, b_Wih, b_bih);

    brios_main_kernel<<<2 * NCTA_PER_DIR, NTHREADS>>>(
        dt,
        f_Whh, f_bhh, f_gamma, f_Wout, f_bout,
        b_Whh, b_bhh, b_gamma, b_Wout, b_bout);

    const int n = BB * LL;
    int full = (out_size >= 3 * n) ? 1 : 0;
    brios_combine_kernel<<<(n + 255) / 256, 256>>>(out, full);
}

// round 17
// speedup vs baseline: 2.4136x; 2.4136x over previous
#include <cuda_runtime.h>

#define BB 512
#define LL 1024
#define DD 16
#define HH 64
#define NB 7        // sequences per CTA
#define NTHREADS 256
#define NCTA_PER_DIR 74   // 148 CTAs total = 1/SM
#define HROW 72     // padded h row: chunk0 cols @ [0,32), chunk1 cols @ [36,68)

typedef unsigned long long ull;

// scratch for y_f (offset 0) and y_b (offset B*L) — static device global (no alloc)
__device__ float g_scratch[2 * BB * LL];

__device__ __forceinline__ void fma2(ull &acc, ull a, ull b) {
    asm("fma.rn.f32x2 %0, %1, %2, %0;" : "+l"(acc) : "l"(a), "l"(b));
}
__device__ __forceinline__ float unpack_sum(ull v) {
    float lo, hi;
    asm("mov.b64 {%0, %1}, %2;" : "=f"(lo), "=f"(hi) : "l"(v));
    return lo + hi;
}
__device__ __forceinline__ ull pack2(float lo, float hi) {
    ull r;
    asm("mov.b64 %0, {%1, %2};" : "=l"(r) : "f"(lo), "f"(hi));
    return r;
}
__device__ __forceinline__ ull add2(ull a, ull b) {
    ull r;
    asm("add.rn.f32x2 %0, %1, %2;" : "=l"(r) : "l"(a), "l"(b));
    return r;
}
__device__ __forceinline__ void unpack2(ull v, float &lo, float &hi) {
    asm("mov.b64 {%0, %1}, %2;" : "=f"(lo), "=f"(hi) : "l"(v));
}
__device__ __forceinline__ float sigmoidf_(float x) {
    return 1.0f / (1.0f + __expf(-x));
}
__device__ __forceinline__ float tanhf_(float x) {
    float ax = fabsf(x);
    float e  = __expf(2.0f * ax);          // inf-safe
    float t  = 1.0f - 2.0f / (e + 1.0f);
    return copysignf(t, x);
}

// group-local barrier: id 1 for sg0, id 2 for sg1 (id 0 = default barrier)
#define GROUP_BAR(id) asm volatile("bar.sync %0, 128;" :: "r"(id) : "memory")

__global__ void brios_dummy_kernel() {}   // ncu launch-skip alignment

// One fused step for NSEQ sequences starting at SBASE.
// Thread owns Whh rows {u, 64+u, 128+u} x cols [chunk*32, chunk*32+32),
// and Wih rows {u,64+u,128+u} x cols [chunk*8, chunk*8+8).
template<int NSEQ>
__device__ __forceinline__ void step_work(
    int SBASE, int chunk, int u, int w4, int hslot,
    const ull (&whh2)[3][16], const ull (&wih2)[3][4],
    const float (&bhh3)[3], const float (&bih3)[3], float wout_u,
    const float* __restrict__ h_rd, float* __restrict__ h_wr,
    const float* __restrict__ x_rd, const float* __restrict__ decay_rd,
    float* __restrict__ ypart_wr)
{
    ull acc[NSEQ][3];
    #pragma unroll
    for (int s = 0; s < NSEQ; s++) { acc[s][0] = 0; acc[s][1] = 0; acc[s][2] = 0; }

    #pragma unroll
    for (int kp = 0; kp < 8; kp++) {          // 8 x 16B = 32 cols (half row)
        #pragma unroll
        for (int s = 0; s < NSEQ; s++) {
            ulonglong2 hh = reinterpret_cast<const ulonglong2*>(
                h_rd + (SBASE + s) * HROW + chunk * 36)[kp];
            fma2(acc[s][0], whh2[0][2 * kp],     hh.x);
            fma2(acc[s][0], whh2[0][2 * kp + 1], hh.y);
            fma2(acc[s][1], whh2[1][2 * kp],     hh.x);
            fma2(acc[s][1], whh2[1][2 * kp + 1], hh.y);
            fma2(acc[s][2], whh2[2][2 * kp],     hh.x);
            fma2(acc[s][2], whh2[2][2 * kp + 1], hh.y);
        }
    }

    float ghs[NSEQ][3], gis[NSEQ][3];
    #pragma unroll
    for (int s = 0; s < NSEQ; s++) {
        const ulonglong2* xp = reinterpret_cast<const ulonglong2*>(
            x_rd + (SBASE + s) * DD + chunk * 8);
        ulonglong2 x0 = xp[0], x1 = xp[1];
        ull g0 = 0, g1 = 0, g2 = 0;
        fma2(g0, wih2[0][0], x0.x); fma2(g0, wih2[0][1], x0.y);
        fma2(g0, wih2[0][2], x1.x); fma2(g0, wih2[0][3], x1.y);
        fma2(g1, wih2[1][0], x0.x); fma2(g1, wih2[1][1], x0.y);
        fma2(g1, wih2[1][2], x1.x); fma2(g1, wih2[1][3], x1.y);
        fma2(g2, wih2[2][0], x0.x); fma2(g2, wih2[2][1], x0.y);
        fma2(g2, wih2[2][2], x1.x); fma2(g2, wih2[2][3], x1.y);

        ull P0 = pack2(unpack_sum(acc[s][0]), unpack_sum(acc[s][1]));
        ull P1 = pack2(unpack_sum(acc[s][2]), unpack_sum(g0));
        ull P2 = pack2(unpack_sum(g1),        unpack_sum(g2));
        P0 = add2(P0, __shfl_xor_sync(0xffffffffu, P0, 1));
        P1 = add2(P1, __shfl_xor_sync(0xffffffffu, P1, 1));
        P2 = add2(P2, __shfl_xor_sync(0xffffffffu, P2, 1));
        unpack2(P0, ghs[s][0], ghs[s][1]);
        unpack2(P1, ghs[s][2], gis[s][0]);
        unpack2(P2, gis[s][1], gis[s][2]);
    }

    // gate: lane parity (=chunk) handles seq 2*pair+chunk; short 2-shfl reduce
    const int lane = threadIdx.x & 31;
    #pragma unroll
    for (int pair = 0; pair < (NSEQ + 1) / 2; pair++) {
        const int s0i = 2 * pair;
        const int s1i = (2 * pair + 1 < NSEQ) ? (2 * pair + 1) : 0;
        const bool valid = !(chunk && (2 * pair + 1 >= NSEQ));
        const int smi = chunk ? s1i : s0i;
        float c = 0.0f;
        int S = SBASE + smi;
        if (valid) {
            float GR = chunk ? ghs[s1i][0] : ghs[s0i][0];
            float GZ = chunk ? ghs[s1i][1] : ghs[s0i][1];
            float GN = chunk ? ghs[s1i][2] : ghs[s0i][2];
            float IR = chunk ? gis[s1i][0] : gis[s0i][0];
            float IZ = chunk ? gis[s1i][1] : gis[s0i][1];
            float IN = chunk ? gis[s1i][2] : gis[s0i][2];
            float dk = decay_rd[S];
            float rr = sigmoidf_((IR + bih3[0]) + fmaf(dk, GR, bhh3[0]));
            float zz = sigmoidf_((IZ + bih3[1]) + fmaf(dk, GZ, bhh3[1]));
            float nn = tanhf_   ((IN + bih3[2]) + rr * fmaf(dk, GN, bhh3[2]));
            float hb = h_rd[S * HROW + hslot] * dk;
            float hnew = (1.0f - zz) * nn + zz * hb;
            h_wr[S * HROW + hslot] = hnew;
            c = hnew * wout_u;
        }
        // 2-shfl partial reduce: 4 partials per warp per parity
        c += __shfl_xor_sync(0xffffffffu, c, 2);
        c += __shfl_xor_sync(0xffffffffu, c, 4);
        if (valid && ((lane & 6) == 0))
            ypart_wr[S * 16 + w4 * 4 + (lane >> 3)] = c;
    }
}

__global__ __launch_bounds__(NTHREADS, 1)
void brios_main_kernel(
    const float* __restrict__ x,  const float* __restrict__ dt,
    const float* __restrict__ f_Wih, const float* __restrict__ f_Whh,
    const float* __restrict__ f_bih, const float* __restrict__ f_bhh,
    const float* __restrict__ f_gamma, const float* __restrict__ f_Wout,
    const float* __restrict__ f_bout,
    const float* __restrict__ b_Wih, const float* __restrict__ b_Whh,
    const float* __restrict__ b_bih, const float* __restrict__ b_bhh,
    const float* __restrict__ b_gamma, const float* __restrict__ b_Wout,
    const float* __restrict__ b_bout)
{
    __shared__ __align__(16) float h_sh[2][NB * HROW];
    __shared__ __align__(16) float x_sh[2][NB * DD];
    __shared__ float decay_sh[2][8];
    __shared__ __align__(16) float ypart[2][NB * 16];

    const int tid  = threadIdx.x;
    const int dir  = blockIdx.x / NCTA_PER_DIR;
    const int tile = blockIdx.x % NCTA_PER_DIR;
    const int b0   = tile * NB;

    const float* Wih  = dir ? b_Wih  : f_Wih;
    const float* Whh  = dir ? b_Whh  : f_Whh;
    const float* bih  = dir ? b_bih  : f_bih;
    const float* bhh  = dir ? b_bhh  : f_bhh;
    const float* Wout = dir ? b_Wout : f_Wout;
    const float  bout0 = dir ? b_bout[0] : f_bout[0];
    float g = dir ? b_gamma[0] : f_gamma[0];
    g = fminf(fmaxf(g, 1e-4f), 10.0f);

    float* yout = g_scratch + dir * (BB * LL);

    // two INDEPENDENT groups: sg0 = seqs 0-3, sg1 = seqs 4-6 (own staging each)
    const int sg    = tid >> 7;          // group id
    const int barid = 1 + sg;            // named barrier per group
    const int l     = tid & 127;         // index within group
    const int nseq  = sg ? 3 : 4;
    const int sbase = sg ? 4 : 0;
    const int u     = l >> 1;
    const int chunk = tid & 1;
    const int w4    = (tid >> 5) & 3;
    const int hslot = u + ((u >> 5) << 2);

    // ---- resident weights: gate-triplet rows {u, 64+u, 128+u}, col half ----
    ull whh2[3][16];
    ull wih2[3][4];
    float bhh3[3], bih3[3];
    #pragma unroll
    for (int r = 0; r < 3; r++) {
        int row = u + r * HH;
        const ull* p = reinterpret_cast<const ull*>(Whh + row * HH + chunk * 32);
        #pragma unroll
        for (int k = 0; k < 16; k++) whh2[r][k] = p[k];
        const ull* q = reinterpret_cast<const ull*>(Wih + row * DD + chunk * 8);
        #pragma unroll
        for (int k = 0; k < 4; k++) wih2[r][k] = q[k];
        bhh3[r] = bhh[row];
        bih3[r] = bih[row];
    }
    const float wout_u = Wout[u];

    // staging roles (within group)
    const bool is_x = (l < nseq * DD);
    int xs = 0, xd = 0, x_bb = 0;
    if (is_x) {
        xs = sbase + (l >> 4); xd = l & 15;
        x_bb = min(b0 + xs, BB - 1);
    }
    const bool is_d = (l >= 112) && (l < 112 + nseq);
    const int  ds   = sbase + (l - 112);
    int d_bb = 0;
    if (is_d) d_bb = min(b0 + ds, BB - 1);

    // zero both h buffers (full CTA, then one full barrier before groups split)
    for (int i = tid; i < 2 * NB * HROW; i += NTHREADS) ((float*)h_sh)[i] = 0.0f;

    // ---- prologue: publish x(0)/decay(0), prefetch t=1 ----
    float xr = 0.0f, dtr = 0.0f;
    {
        int t0a = dir ? (LL - 1) : 0;
        int t1a = dir ? (LL - 2) : 1;
        if (is_x) {
            x_sh[0][xs * DD + xd] = x[(x_bb * LL + t0a) * DD + xd];
            xr = x[(x_bb * LL + t1a) * DD + xd];
        }
        if (is_d) {
            float dc = fminf(fmaxf(dt[d_bb * LL + t0a], 0.0f), 1.0e6f);
            decay_sh[0][ds] = __expf(-g * dc);
            dtr = dt[d_bb * LL + t1a];
        }
    }
    __syncthreads();   // single full sync; groups are independent afterwards

    for (int t = 0; t < LL; t++) {
        const int cb = t & 1;
        const int pb = cb ^ 1;

        // ---- group-local staging: x/decay for t+1, emit y(t-1), fetch t+2 ----
        if (is_x) {
            x_sh[pb][xs * DD + xd] = xr;
            int tn  = (t + 2 < LL) ? (t + 2) : (LL - 1);
            int ttn = dir ? (LL - 1 - tn) : tn;
            xr = x[(x_bb * LL + ttn) * DD + xd];
        }
        if (is_d) {
            if (t > 0) {
                int b = b0 + ds;
                if (b < BB) {
                    int tprev = dir ? (LL - t) : (t - 1);
                    const float4* yp =
                        reinterpret_cast<const float4*>(&ypart[pb][ds * 16]);
                    float4 a0 = yp[0], a1 = yp[1], a2 = yp[2], a3 = yp[3];
                    float ssum = (a0.x + a0.y + a0.z + a0.w)
                               + (a1.x + a1.y + a1.z + a1.w)
                               + (a2.x + a2.y + a2.z + a2.w)
                               + (a3.x + a3.y + a3.z + a3.w);
                    yout[b * LL + tprev] = ssum + bout0;
                }
            }
            float dc = fminf(fmaxf(dtr, 0.0f), 1.0e6f);
            decay_sh[pb][ds] = __expf(-g * dc);
            int tn  = (t + 2 < LL) ? (t + 2) : (LL - 1);
            int ttn = dir ? (LL - 1 - tn) : tn;
            dtr = dt[d_bb * LL + ttn];
        }

        // ---- matvec + gate (group-scoped) ----
        if (sg == 0) {
            step_work<4>(0, chunk, u, w4, hslot, whh2, wih2, bhh3, bih3, wout_u,
                         h_sh[pb], h_sh[cb], x_sh[cb], decay_sh[cb], ypart[cb]);
        } else {
            step_work<3>(4, chunk, u, w4, hslot, whh2, wih2, bhh3, bih3, wout_u,
                         h_sh[pb], h_sh[cb], x_sh[cb], decay_sh[cb], ypart[cb]);
        }
        GROUP_BAR(barid);
    }

    // final y (step t = L-1): group bar already passed after last gate
    if (is_d) {
        int b = b0 + ds;
        if (b < BB) {
            int tlast = dir ? 0 : (LL - 1);
            const float4* yp =
                reinterpret_cast<const float4*>(&ypart[(LL - 1) & 1][ds * 16]);
            float4 a0 = yp[0], a1 = yp[1], a2 = yp[2], a3 = yp[3];
            float ssum = (a0.x + a0.y + a0.z + a0.w)
                       + (a1.x + a1.y + a1.z + a1.w)
                       + (a2.x + a2.y + a2.z + a2.w)
                       + (a3.x + a3.y + a3.z + a3.w);
            yout[b * LL + tlast] = ssum + bout0;
        }
    }
}

__global__ void brios_combine_kernel(float* __restrict__ out, int full) {
    int i = blockIdx.x * blockDim.x + threadIdx.x;
    const int n = BB * LL;
    if (i < n) {
        float a = g_scratch[i];          // y_f
        float b = g_scratch[n + i];      // y_b
        out[i] = 0.5f * (a + b);
        if (full) {
            out[n + i]     = a;
            out[2 * n + i] = b;
        }
    }
}

extern "C" void kernel_launch(void* const* d_in, const int* in_sizes, int n_in,
                              void* d_out, int out_size) {
    const float* x       = (const float*)d_in[0];
    const float* dt      = (const float*)d_in[1];
    const float* f_Wih   = (const float*)d_in[2];
    const float* f_Whh   = (const float*)d_in[3];
    const float* f_bih   = (const float*)d_in[4];
    const float* f_bhh   = (const float*)d_in[5];
    const float* f_gamma = (const float*)d_in[6];
    const float* f_Wout  = (const float*)d_in[7];
    const float* f_bout  = (const float*)d_in[8];
    const float* b_Wih   = (const float*)d_in[9];
    const float* b_Whh   = (const float*)d_in[10];
    const float* b_bih   = (const float*)d_in[11];
    const float* b_bhh   = (const float*)d_in[12];
    const float* b_gamma = (const float*)d_in[13];
    const float* b_Wout  = (const float*)d_in[14];
    const float* b_bout  = (const float*)d_in[15];
    float* out = (float*)d_out;

    // 3 dummies: aligns ncu "-s 5 -c 1" onto brios_main_kernel (verified R11/R12)
    for (int i = 0; i < 3; i++) brios_dummy_kernel<<<1, 32>>>();

    brios_main_kernel<<<2 * NCTA_PER_DIR, NTHREADS>>>(
        x, dt,
        f_Wih, f_Whh, f_bih, f_bhh, f_gamma, f_Wout, f_bout,
        b_Wih, b_Whh, b_bih, b_bhh, b_gamma, b_Wout, b_bout);

    const int n = BB * LL;
    int full = (out_size >= 3 * n) ? 1 : 0;
    brios_combine_kernel<<<(n + 255) / 256, 256>>>(out, full);
}